// round 17
// baseline (speedup 1.0000x reference)
#include <cuda_runtime.h>

// Fused DisplaceChannel (integer shift, zero fill) + separable Gaussian 3x3
// depthwise conv, register-pipelined, no shared memory.
// 4 rows/iteration with one-iteration-ahead software prefetch
// (8 LDG.128 in flight steady-state), streaming (__stcs) stores.
//
// inp:    (B=16, C=192, H=128, W=128) fp32
// offset: (P=48, 2) fp32, layout [x, y]
//
// out(y,x) = sum_{ky,kx} wy[ky]*wx[kx] * shifted(y+ky-1, x+kx-1)
//   shifted(yy,xx) = inp(yy-Ry, xx-Rx) if yy,xx,yy-Ry,xx-Rx all in range else 0
//   (Rx,Ry) = round-half-even(offset)   [rintf == jnp.round]
//   wx,wy   = normalized 1D Gaussians of the fractional residual (sigma=0.5);
//             the 2D kernel and its normalizer factorize exactly.

namespace {
constexpr int H = 128;
constexpr int W = 128;
constexpr int C = 192;            // 48 positions * 4 channels each
constexpr int ROWS_PER_WARP = 16; // 8 warps x 16 rows = 128-row plane
}

__global__ __launch_bounds__(256, 3)
void displace_lo_kernel(const float* __restrict__ inp,
                        const float* __restrict__ offset,
                        float* __restrict__ out) {
    const int plane = blockIdx.x;            // b*C + c
    const int p     = (plane % C) >> 2;      // position (cpp = 4)
    const int wid   = threadIdx.x >> 5;
    const int lane  = threadIdx.x & 31;
    const int x4    = lane << 2;             // output col base (multiple of 4)

    // ---- separable Gaussian weights from the fractional residual ----
    const float ox = offset[2 * p + 0];
    const float oy = offset[2 * p + 1];
    const float rx = rintf(ox), ry = rintf(oy);   // round-half-even == jnp.round
    const int   Rx = (int)rx,  Ry = (int)ry;
    const float dx = ox - rx,  dy = oy - ry;

    float wx0, wx1, wx2, wy0, wy1, wy2;
    {
        const float fx0 = -1.f + dx, fx1 = dx, fx2 = 1.f + dx;
        const float fy0 = -1.f + dy, fy1 = dy, fy2 = 1.f + dy;
        // 1/(2*sigma^2) = 2 for sigma = 0.5
        const float ex0 = expf(-2.f * fx0 * fx0);
        const float ex1 = expf(-2.f * fx1 * fx1);
        const float ex2 = expf(-2.f * fx2 * fx2);
        const float ey0 = expf(-2.f * fy0 * fy0);
        const float ey1 = expf(-2.f * fy1 * fy1);
        const float ey2 = expf(-2.f * fy2 * fy2);
        const float isx = 1.f / (ex0 + ex1 + ex2);
        const float isy = 1.f / (ey0 + ey1 + ey2);
        wx0 = ex0 * isx; wx1 = ex1 * isx; wx2 = ex2 * isx;
        wy0 = ey0 * isy; wy1 = ey1 * isy; wy2 = ey2 * isy;
    }

    const float* __restrict__ ip = inp + (size_t)plane * (H * W);
    float* __restrict__       op = out + (size_t)plane * (H * W);
    // source-row pointer pre-shifted by the integer displacement
    const float* __restrict__ ipsh = ip - (ptrdiff_t)Ry * W;

    const int  r0      = wid * ROWS_PER_WARP;
    const bool aligned = ((Rx & 3) == 0);    // block-uniform branch
    const int  cA      = x4 - Rx;            // aligned-case source col base

    // Raw shifted-row load (zeros for conv-pad rows / displaced-out pixels).
    auto vload = [&](int y) -> float4 {
        float4 v = make_float4(0.f, 0.f, 0.f, 0.f);
        const int ys = y - Ry;
        if (((unsigned)y < (unsigned)H) & ((unsigned)ys < (unsigned)H)) {
            const float* src = ipsh + y * W;
            if (aligned) {
                if ((unsigned)cA <= (unsigned)(W - 4))   // all-in or all-out
                    v = *(const float4*)(src + cA);
            } else {
                float* vf = (float*)&v;
#pragma unroll
                for (int j = 0; j < 4; ++j) {
                    const int c = x4 + j - Rx;
                    if ((unsigned)c < (unsigned)W) vf[j] = src[c];
                }
            }
        }
        return v;
    };

    // Horizontal 3-tap; lane edges supply the x = -1 / W zero pad.
    auto hpass = [&](float4 v) -> float4 {
        float el = __shfl_up_sync(0xffffffffu, v.w, 1);
        float er = __shfl_down_sync(0xffffffffu, v.x, 1);
        if (lane == 0)  el = 0.f;
        if (lane == 31) er = 0.f;
        float4 h;
        h.x = wx0 * el  + wx1 * v.x + wx2 * v.y;
        h.y = wx0 * v.x + wx1 * v.y + wx2 * v.z;
        h.z = wx0 * v.y + wx1 * v.z + wx2 * v.w;
        h.w = wx0 * v.z + wx1 * v.w + wx2 * er;
        return h;
    };

    // ---- vertical 3-tap, 4 rows/iteration, prefetch next batch before
    // consuming the current one (8 loads in flight steady-state). ----
    float4 vC = vload(r0 + 1);
    float4 vD = vload(r0 + 2);
    float4 vE = vload(r0 + 3);
    float4 vF = vload(r0 + 4);
    float4 hA = hpass(vload(r0 - 1));
    float4 hB = hpass(vload(r0));

#pragma unroll
    for (int i = 0; i < ROWS_PER_WARP; i += 4) {
        // prefetch next iteration's rows (statically elided on last iter)
        float4 nC, nD, nE, nF;
        if (i + 4 < ROWS_PER_WARP) {
            nC = vload(r0 + 5 + i);
            nD = vload(r0 + 6 + i);
            nE = vload(r0 + 7 + i);
            nF = vload(r0 + 8 + i);
        }

        const float4 hC = hpass(vC);
        const float4 hD = hpass(vD);
        const float4 hE = hpass(vE);
        const float4 hF = hpass(vF);

        float4 o0, o1, o2, o3;
        o0.x = wy0 * hA.x + wy1 * hB.x + wy2 * hC.x;
        o0.y = wy0 * hA.y + wy1 * hB.y + wy2 * hC.y;
        o0.z = wy0 * hA.z + wy1 * hB.z + wy2 * hC.z;
        o0.w = wy0 * hA.w + wy1 * hB.w + wy2 * hC.w;

        o1.x = wy0 * hB.x + wy1 * hC.x + wy2 * hD.x;
        o1.y = wy0 * hB.y + wy1 * hC.y + wy2 * hD.y;
        o1.z = wy0 * hB.z + wy1 * hC.z + wy2 * hD.z;
        o1.w = wy0 * hB.w + wy1 * hC.w + wy2 * hD.w;

        o2.x = wy0 * hC.x + wy1 * hD.x + wy2 * hE.x;
        o2.y = wy0 * hC.y + wy1 * hD.y + wy2 * hE.y;
        o2.z = wy0 * hC.z + wy1 * hD.z + wy2 * hE.z;
        o2.w = wy0 * hC.w + wy1 * hD.w + wy2 * hE.w;

        o3.x = wy0 * hD.x + wy1 * hE.x + wy2 * hF.x;
        o3.y = wy0 * hD.y + wy1 * hE.y + wy2 * hF.y;
        o3.z = wy0 * hD.z + wy1 * hE.z + wy2 * hF.z;
        o3.w = wy0 * hD.w + wy1 * hE.w + wy2 * hF.w;

        // streaming stores: output is write-once, keep L2 for the read stream
        float* orow = op + (r0 + i) * W + x4;
        __stcs((float4*)(orow),         o0);
        __stcs((float4*)(orow + W),     o1);
        __stcs((float4*)(orow + 2 * W), o2);
        __stcs((float4*)(orow + 3 * W), o3);

        hA = hE;
        hB = hF;
        vC = nC; vD = nD; vE = nE; vF = nF;
    }
}

extern "C" void kernel_launch(void* const* d_in, const int* in_sizes, int n_in,
                              void* d_out, int out_size) {
    const float* inp = (const float*)d_in[0];
    const float* off = (const float*)d_in[1];
    float*       out = (float*)d_out;

    const int planes = in_sizes[0] / (H * W);   // B*C = 3072
    displace_lo_kernel<<<planes, 256>>>(inp, off, out);
}